// round 16
// baseline (speedup 1.0000x reference)
#include <cuda_runtime.h>
#include <cuda_fp16.h>
#include <math.h>

// Problem constants (fixed by the dataset)
#define Bc   4
#define Nc   50000
#define EcMax 800000
#define INc  128
#define Hc   4
#define Dc   32
#define HDc  128
#define BNc  (Bc * Nc)          // 200000 rows
#define GAT_SLOPE 0.2f
#define ACT_SLOPE 0.01f
#define BN_EPS    1e-5f
#define NSLICE 8

// ---------------- scratch (device globals; no allocation allowed) ----------
__device__ __half   g_featH[(size_t)BNc * HDc]; // 51.2 MB (fp16 features)
__device__ __half   g_aggH[(size_t)BNc * HDc];  // 51.2 MB (fp16 pre-BN agg)
__device__ __half   g_Wh[HDc * HDc];            // W transposed [col][k], fp16
// exp-factored attention terms: [2n] = exp(v), [2n+1] = exp(0.2 v), per head
__device__ float4   g_elp[2 * BNc];
__device__ float4   g_erp[2 * BNc];
__device__ int      g_cnt[Nc];                  // in-degree histogram
__device__ int      g_off[Nc + 1];              // CSR offsets
__device__ int      g_wr[Nc];                   // scatter write cursors
__device__ int      g_csrc[EcMax];              // CSR: src node per slot
__device__ float    g_psum[NSLICE][HDc];        // sliced BN sum accumulators
__device__ float    g_psq[NSLICE][HDc];         // sliced BN sq accumulators

__device__ __forceinline__ float leaky(float v, float s) {
    return v >= 0.0f ? v : s * v;
}

__device__ __forceinline__ void mma_f16(float* c, const unsigned* a,
                                        unsigned b0, unsigned b1) {
    asm volatile(
        "mma.sync.aligned.m16n8k16.row.col.f32.f16.f16.f32 "
        "{%0,%1,%2,%3}, {%4,%5,%6,%7}, {%8,%9}, {%0,%1,%2,%3};"
        : "+f"(c[0]), "+f"(c[1]), "+f"(c[2]), "+f"(c[3])
        : "r"(a[0]), "r"(a[1]), "r"(a[2]), "r"(a[3]), "r"(b0), "r"(b1));
}

// ---------------- 0: zero-init histogram + BN accumulators ------------------
__global__ void k_init() {
    int i = blockIdx.x * blockDim.x + threadIdx.x;
    int stride = gridDim.x * blockDim.x;
    for (int p = i; p < Nc; p += stride) g_cnt[p] = 0;
    if (i < NSLICE * HDc) {
        ((float*)g_psum)[i] = 0.f;
        ((float*)g_psq)[i] = 0.f;
    }
}

// ---------------- 0b: W -> fp16 transposed [col][k] --------------------------
__global__ void k_prepW(const float* __restrict__ W) {
    int i = blockIdx.x * blockDim.x + threadIdx.x;  // 0..16383
    int k = i >> 7, c = i & 127;
    g_Wh[c * 128 + k] = __float2half_rn(W[k * 128 + c]);
}

// ---------------- CSR build --------------------------------------------------
__global__ void k_hist(const int* __restrict__ dst, int E) {
    int e = blockIdx.x * blockDim.x + threadIdx.x;
    if (e < E) atomicAdd(&g_cnt[dst[e]], 1);
}

__global__ void k_scan() {
    __shared__ int ssum[1024];
    const int t = threadIdx.x;
    const int per = (Nc + 1023) / 1024;   // 49
    const int base = t * per;
    int s = 0;
    for (int i = 0; i < per; i++) {
        int idx = base + i;
        if (idx < Nc) s += g_cnt[idx];
    }
    ssum[t] = s;
    __syncthreads();
    for (int o = 1; o < 1024; o <<= 1) {
        int v = (t >= o) ? ssum[t - o] : 0;
        __syncthreads();
        ssum[t] += v;
        __syncthreads();
    }
    int run = ssum[t] - s;
    for (int i = 0; i < per; i++) {
        int idx = base + i;
        if (idx < Nc) {
            g_off[idx] = run;
            g_wr[idx]  = run;
            run += g_cnt[idx];
        }
    }
    if (t == 1023) g_off[Nc] = ssum[1023];
}

__global__ void k_scatter(const int* __restrict__ src, const int* __restrict__ dst, int E) {
    int e = blockIdx.x * blockDim.x + threadIdx.x;
    if (e < E) {
        int pos = atomicAdd(&g_wr[dst[e]], 1);
        g_csrc[pos] = src[e];
    }
}

// ---------------- 1: feat = x @ W via fp16 mma (m16n8k16) -------------------
// Block 256 threads (8 warps, 2m x 4n), block tile 64x128, warp tile 32x32.
// Epilogue additionally precomputes the exp-factored attention terms.
#define LDK 136
#define SMEM_GEMM ((64 + 128) * LDK * 2 + 2048)
__global__ void __launch_bounds__(256, 3)
k_gemm(const float* __restrict__ x,
       const float* __restrict__ attn_l, const float* __restrict__ attn_r) {
    extern __shared__ __half sm[];
    __half* xs = sm;                       // [64][LDK]
    __half* Wt = sm + 64 * LDK;            // [128][LDK]
    float* sEl = (float*)(sm + 192 * LDK); // [64][4]
    float* sEr = sEl + 256;                // [64][4]

    const int t = threadIdx.x;
    const int lane = t & 31, warp = t >> 5;
    const int wm = warp >> 2, wn = warp & 3;   // warp grid 2m x 4n
    const int gid = lane >> 2, tig = lane & 3;
    const int row0 = blockIdx.x * 64;

    sEl[t] = 0.f;
    sEr[t] = 0.f;

#pragma unroll
    for (int i = 0; i < 8; i++) {
        int idx = i * 256 + t;
        int c = idx >> 4, kg = idx & 15;
        uint4 v = *(const uint4*)(g_Wh + c * 128 + kg * 8);
        *(uint4*)(Wt + c * LDK + kg * 8) = v;
    }
#pragma unroll
    for (int i = 0; i < 8; i++) {
        int idx = i * 256 + t;
        int r = idx >> 5, kg = idx & 31;
        float4 v = *(const float4*)(x + (size_t)(row0 + r) * 128 + kg * 4);
        __half2 h0 = __floats2half2_rn(v.x, v.y);
        __half2 h1 = __floats2half2_rn(v.z, v.w);
        uint2 pk;
        pk.x = *(unsigned*)&h0;
        pk.y = *(unsigned*)&h1;
        *(uint2*)(xs + r * LDK + kg * 4) = pk;
    }
    __syncthreads();

    float acc[2][4][4];
#pragma unroll
    for (int i = 0; i < 2; i++)
#pragma unroll
        for (int j = 0; j < 4; j++)
#pragma unroll
            for (int r = 0; r < 4; r++) acc[i][j][r] = 0.f;

#pragma unroll
    for (int ks = 0; ks < 8; ks++) {
        const int k0 = ks * 16;
        unsigned a[2][4];
#pragma unroll
        for (int mt = 0; mt < 2; mt++) {
            int rb = wm * 32 + mt * 16;
            a[mt][0] = *(const unsigned*)(xs + (rb + gid) * LDK + k0 + 2 * tig);
            a[mt][1] = *(const unsigned*)(xs + (rb + gid + 8) * LDK + k0 + 2 * tig);
            a[mt][2] = *(const unsigned*)(xs + (rb + gid) * LDK + k0 + 2 * tig + 8);
            a[mt][3] = *(const unsigned*)(xs + (rb + gid + 8) * LDK + k0 + 2 * tig + 8);
        }
#pragma unroll
        for (int nt = 0; nt < 4; nt++) {
            int cb = wn * 32 + nt * 8;
            unsigned b0 = *(const unsigned*)(Wt + (cb + gid) * LDK + k0 + 2 * tig);
            unsigned b1 = *(const unsigned*)(Wt + (cb + gid) * LDK + k0 + 2 * tig + 8);
#pragma unroll
            for (int mt = 0; mt < 2; mt++)
                mma_f16(acc[mt][nt], a[mt], b0, b1);
        }
    }

    // epilogue: store feat (fp16) + accumulate el/er into smem
#pragma unroll
    for (int mt = 0; mt < 2; mt++) {
        int lr0 = wm * 32 + mt * 16 + gid;
        int lr1 = lr0 + 8;
        float el0 = 0.f, el1 = 0.f, er0 = 0.f, er1 = 0.f;
#pragma unroll
        for (int nt = 0; nt < 4; nt++) {
            int c = wn * 32 + nt * 8 + tig * 2;
            float alc0 = attn_l[c], alc1 = attn_l[c + 1];
            float arc0 = attn_r[c], arc1 = attn_r[c + 1];
            float* a4 = acc[mt][nt];
            el0 += a4[0] * alc0 + a4[1] * alc1;
            er0 += a4[0] * arc0 + a4[1] * arc1;
            el1 += a4[2] * alc0 + a4[3] * alc1;
            er1 += a4[2] * arc0 + a4[3] * arc1;
            *(__half2*)(g_featH + (size_t)(row0 + lr0) * 128 + c) =
                __floats2half2_rn(a4[0], a4[1]);
            *(__half2*)(g_featH + (size_t)(row0 + lr1) * 128 + c) =
                __floats2half2_rn(a4[2], a4[3]);
        }
        atomicAdd(&sEl[lr0 * 4 + wn], el0);
        atomicAdd(&sEl[lr1 * 4 + wn], el1);
        atomicAdd(&sEr[lr0 * 4 + wn], er0);
        atomicAdd(&sEr[lr1 * 4 + wn], er1);
    }
    __syncthreads();
    if (t < 64) {
        size_t n = row0 + t;
        float4 el = make_float4(sEl[t * 4], sEl[t * 4 + 1], sEl[t * 4 + 2], sEl[t * 4 + 3]);
        float4 er = make_float4(sEr[t * 4], sEr[t * 4 + 1], sEr[t * 4 + 2], sEr[t * 4 + 3]);
        g_elp[2 * n] = make_float4(__expf(el.x), __expf(el.y), __expf(el.z), __expf(el.w));
        g_elp[2 * n + 1] = make_float4(__expf(GAT_SLOPE * el.x), __expf(GAT_SLOPE * el.y),
                                       __expf(GAT_SLOPE * el.z), __expf(GAT_SLOPE * el.w));
        g_erp[2 * n] = make_float4(__expf(er.x), __expf(er.y), __expf(er.z), __expf(er.w));
        g_erp[2 * n + 1] = make_float4(__expf(GAT_SLOPE * er.x), __expf(GAT_SLOPE * er.y),
                                       __expf(GAT_SLOPE * er.z), __expf(GAT_SLOPE * er.w));
    }
}

// ---------------- 2: fused edge-softmax + gather agg + BN partial stats -----
// grid (Nc), 128 threads: block = one node, warp = one batch,
// lane = 4 channels (one uint2 = 8B gather per edge, LDG.64, 256B/warp).
// MUFU-free weights: exp(leaky(el+er)) = p1*q1 if p1*q1>=1 else p2*q2
// (p = exp(el), exp(0.2 el); q = exp(er), exp(0.2 er)).
#define CHb 32
__global__ void __launch_bounds__(128, 16) k_agg() {
    const int n = blockIdx.x;
    const int tid = threadIdx.x;
    const int lane = tid & 31;         // channels 4*lane .. 4*lane+3
    const int b = tid >> 5;            // batch = warp
    const int h = lane >> 3;           // head
    const int off0 = g_off[n];
    const int deg  = g_off[n + 1] - off0;
    const size_t nb = (size_t)b * Nc + n;

    if (deg == 0) {
        *(uint2*)(g_aggH + nb * 128 + lane * 4) = make_uint2(0u, 0u);
        return;
    }

    __shared__ int   ssrc[CHb];
    __shared__ float sw[CHb][4][4];   // [edge][batch][head]
    __shared__ float sS[4][HDc];      // [batch][channel] partial sums
    __shared__ float sQ[4][HDc];

    // per-warp-uniform er exp pair (broadcast loads)
    const float4 q1 = g_erp[2 * nb];
    const float4 q2 = g_erp[2 * nb + 1];

    float a0 = 0.f, a1 = 0.f, a2 = 0.f, a3 = 0.f, wsum = 0.f;

    for (int base = 0; base < deg; base += CHb) {
        int cnt = min(CHb, deg - base);
        if (lane < cnt) {
            int s = g_csrc[off0 + base + lane];
            if (b == 0) ssrc[lane] = s;
            size_t idx = 2 * ((size_t)b * Nc + s);
            float4 p1 = g_elp[idx];
            float4 p2 = g_elp[idx + 1];
            float tx = p1.x * q1.x, ty = p1.y * q1.y;
            float tz = p1.z * q1.z, tw = p1.w * q1.w;
            sw[lane][b][0] = (tx >= 1.f) ? tx : p2.x * q2.x;
            sw[lane][b][1] = (ty >= 1.f) ? ty : p2.y * q2.y;
            sw[lane][b][2] = (tz >= 1.f) ? tz : p2.z * q2.z;
            sw[lane][b][3] = (tw >= 1.f) ? tw : p2.w * q2.w;
        }
        __syncthreads();
#pragma unroll 4
        for (int j = 0; j < cnt; j++) {
            int s = ssrc[j];
            float w = sw[j][b][h];
            wsum += w;
            uint2 u = *(const uint2*)(g_featH + ((size_t)b * Nc + s) * 128 + lane * 4);
            float2 f0 = __half22float2(*(const __half2*)&u.x);
            float2 f1 = __half22float2(*(const __half2*)&u.y);
            a0 += w * f0.x; a1 += w * f0.y;
            a2 += w * f1.x; a3 += w * f1.y;
        }
        __syncthreads();
    }
    float inv = 1.f / fmaxf(wsum, 1e-9f);
    float o0 = a0 * inv, o1 = a1 * inv, o2 = a2 * inv, o3 = a3 * inv;
    {
        __half2 h0 = __floats2half2_rn(o0, o1);
        __half2 h1 = __floats2half2_rn(o2, o3);
        uint2 pk;
        pk.x = *(unsigned*)&h0;
        pk.y = *(unsigned*)&h1;
        *(uint2*)(g_aggH + nb * 128 + lane * 4) = pk;
    }

    // BN partial stats from fp32 values: smem pre-reduce, then sliced atomics
    sS[b][lane * 4 + 0] = o0; sS[b][lane * 4 + 1] = o1;
    sS[b][lane * 4 + 2] = o2; sS[b][lane * 4 + 3] = o3;
    sQ[b][lane * 4 + 0] = o0 * o0; sQ[b][lane * 4 + 1] = o1 * o1;
    sQ[b][lane * 4 + 2] = o2 * o2; sQ[b][lane * 4 + 3] = o3 * o3;
    __syncthreads();
    {
        int ch = tid;  // 128 threads, 128 channels
        int sl = n & (NSLICE - 1);
        atomicAdd(&g_psum[sl][ch], sS[0][ch] + sS[1][ch] + sS[2][ch] + sS[3][ch]);
        atomicAdd(&g_psq[sl][ch],  sQ[0][ch] + sQ[1][ch] + sQ[2][ch] + sQ[3][ch]);
    }
}

// ---------------- 3: BN finalize + apply + LeakyReLU -------------------------
__global__ void __launch_bounds__(256)
k_bnapply(float4* out, const float* __restrict__ gamma,
          const float* __restrict__ beta) {
    __shared__ float s_sc[HDc];
    __shared__ float s_sh[HDc];
    const int tid = threadIdx.x;
    if (tid < HDc) {
        float s = 0.f, q = 0.f;
#pragma unroll
        for (int i = 0; i < NSLICE; i++) { s += g_psum[i][tid]; q += g_psq[i][tid]; }
        float mean = s / (float)BNc;
        float var  = q / (float)BNc - mean * mean;
        float sc = gamma[tid] * rsqrtf(var + BN_EPS);
        s_sc[tid] = sc;
        s_sh[tid] = beta[tid] - mean * sc;
    }
    __syncthreads();
    const int c4 = tid & 31;
    const float4 sc = *(const float4*)(s_sc + c4 * 4);
    const float4 sh = *(const float4*)(s_sh + c4 * 4);
    int r = blockIdx.x * 8 + (tid >> 5);
    const int rstride = gridDim.x * 8;
    for (; r < BNc; r += rstride) {
        uint2 u = *(const uint2*)(g_aggH + (size_t)r * 128 + c4 * 4);
        float2 f0 = __half22float2(*(const __half2*)&u.x);
        float2 f1 = __half22float2(*(const __half2*)&u.y);
        float4 v;
        v.x = leaky(f0.x * sc.x + sh.x, ACT_SLOPE);
        v.y = leaky(f0.y * sc.y + sh.y, ACT_SLOPE);
        v.z = leaky(f1.x * sc.z + sh.z, ACT_SLOPE);
        v.w = leaky(f1.y * sc.w + sh.w, ACT_SLOPE);
        out[(size_t)r * 32 + c4] = v;
    }
}

// ---------------- launch -----------------------------------------------------
extern "C" void kernel_launch(void* const* d_in, const int* in_sizes, int n_in,
                              void* d_out, int out_size) {
    const float* xx     = (const float*)d_in[0];
    const float* W      = (const float*)d_in[1];
    const float* attn_l = (const float*)d_in[2];
    const float* attn_r = (const float*)d_in[3];
    const float* gamma  = (const float*)d_in[4];
    const float* beta   = (const float*)d_in[5];
    const int*   src    = (const int*)d_in[6];
    const int*   dst    = (const int*)d_in[7];
    float* out = (float*)d_out;
    const int E = in_sizes[6];

    static cudaStream_t s2 = nullptr;
    static cudaEvent_t evFork = nullptr, evJoin = nullptr;
    if (s2 == nullptr) {
        cudaStreamCreateWithFlags(&s2, cudaStreamNonBlocking);
        cudaEventCreateWithFlags(&evFork, cudaEventDisableTiming);
        cudaEventCreateWithFlags(&evJoin, cudaEventDisableTiming);
        cudaFuncSetAttribute(k_gemm, cudaFuncAttributeMaxDynamicSharedMemorySize,
                             SMEM_GEMM);
    }

    // fork: CSR build on s2, W-prep + GEMM on main stream (independent work)
    cudaEventRecord(evFork, 0);
    cudaStreamWaitEvent(s2, evFork, 0);

    k_init<<<64, 256, 0, s2>>>();
    k_hist<<<(E + 511) / 512, 512, 0, s2>>>(dst, E);
    k_scan<<<1, 1024, 0, s2>>>();
    k_scatter<<<(E + 511) / 512, 512, 0, s2>>>(src, dst, E);
    cudaEventRecord(evJoin, s2);

    k_prepW<<<64, 256>>>(W);
    k_gemm<<<BNc / 64, 256, SMEM_GEMM>>>(xx, attn_l, attn_r);

    cudaStreamWaitEvent(0, evJoin, 0);

    k_agg<<<Nc, 128>>>();

    k_bnapply<<<2048, 256>>>((float4*)out, gamma, beta);
}

// round 17
// speedup vs baseline: 1.0373x; 1.0373x over previous
#include <cuda_runtime.h>
#include <cuda_fp16.h>
#include <math.h>

// Problem constants (fixed by the dataset)
#define Bc   4
#define Nc   50000
#define EcMax 800000
#define INc  128
#define Hc   4
#define Dc   32
#define HDc  128
#define BNc  (Bc * Nc)          // 200000 rows
#define GAT_SLOPE 0.2f
#define ACT_SLOPE 0.01f
#define BN_EPS    1e-5f
#define NSLICE 8

// ---------------- scratch (device globals; no allocation allowed) ----------
__device__ __half   g_featH[(size_t)BNc * HDc]; // 51.2 MB (fp16 features)
__device__ __half   g_aggH[(size_t)BNc * HDc];  // 51.2 MB (fp16 pre-BN agg)
__device__ __half   g_Wh[HDc * HDc];            // W transposed [col][k], fp16
// exp-factored attention terms per (node, head): (exp(v), exp(0.2 v))
__device__ float2   g_elp2[(size_t)BNc * Hc];   // 6.4 MB
__device__ float2   g_erp2[(size_t)BNc * Hc];
__device__ int      g_cnt[Nc];                  // in-degree histogram
__device__ int      g_off[Nc + 1];              // CSR offsets
__device__ int      g_wr[Nc];                   // scatter write cursors
__device__ int      g_csrc[EcMax];              // CSR: src node per slot
__device__ float    g_psum[NSLICE][HDc];        // sliced BN sum accumulators
__device__ float    g_psq[NSLICE][HDc];         // sliced BN sq accumulators

__device__ __forceinline__ float leaky(float v, float s) {
    return v >= 0.0f ? v : s * v;
}

__device__ __forceinline__ void mma_f16(float* c, const unsigned* a,
                                        unsigned b0, unsigned b1) {
    asm volatile(
        "mma.sync.aligned.m16n8k16.row.col.f32.f16.f16.f32 "
        "{%0,%1,%2,%3}, {%4,%5,%6,%7}, {%8,%9}, {%0,%1,%2,%3};"
        : "+f"(c[0]), "+f"(c[1]), "+f"(c[2]), "+f"(c[3])
        : "r"(a[0]), "r"(a[1]), "r"(a[2]), "r"(a[3]), "r"(b0), "r"(b1));
}

// ---------------- 0: zero-init histogram + BN accumulators ------------------
__global__ void k_init() {
    int i = blockIdx.x * blockDim.x + threadIdx.x;
    int stride = gridDim.x * blockDim.x;
    for (int p = i; p < Nc; p += stride) g_cnt[p] = 0;
    if (i < NSLICE * HDc) {
        ((float*)g_psum)[i] = 0.f;
        ((float*)g_psq)[i] = 0.f;
    }
}

// ---------------- 0b: W -> fp16 transposed [col][k] --------------------------
__global__ void k_prepW(const float* __restrict__ W) {
    int i = blockIdx.x * blockDim.x + threadIdx.x;  // 0..16383
    int k = i >> 7, c = i & 127;
    g_Wh[c * 128 + k] = __float2half_rn(W[k * 128 + c]);
}

// ---------------- CSR build --------------------------------------------------
__global__ void k_hist(const int* __restrict__ dst, int E) {
    int e = blockIdx.x * blockDim.x + threadIdx.x;
    if (e < E) atomicAdd(&g_cnt[dst[e]], 1);
}

__global__ void k_scan() {
    __shared__ int ssum[1024];
    const int t = threadIdx.x;
    const int per = (Nc + 1023) / 1024;   // 49
    const int base = t * per;
    int s = 0;
    for (int i = 0; i < per; i++) {
        int idx = base + i;
        if (idx < Nc) s += g_cnt[idx];
    }
    ssum[t] = s;
    __syncthreads();
    for (int o = 1; o < 1024; o <<= 1) {
        int v = (t >= o) ? ssum[t - o] : 0;
        __syncthreads();
        ssum[t] += v;
        __syncthreads();
    }
    int run = ssum[t] - s;
    for (int i = 0; i < per; i++) {
        int idx = base + i;
        if (idx < Nc) {
            g_off[idx] = run;
            g_wr[idx]  = run;
            run += g_cnt[idx];
        }
    }
    if (t == 1023) g_off[Nc] = ssum[1023];
}

__global__ void k_scatter(const int* __restrict__ src, const int* __restrict__ dst, int E) {
    int e = blockIdx.x * blockDim.x + threadIdx.x;
    if (e < E) {
        int pos = atomicAdd(&g_wr[dst[e]], 1);
        g_csrc[pos] = src[e];
    }
}

// ---------------- 1: feat = x @ W via fp16 mma (m16n8k16) -------------------
// Block 256 threads (8 warps, 2m x 4n), block tile 64x128, warp tile 32x32.
// Epilogue precomputes the per-head exp-factored attention terms.
#define LDK 136
#define SMEM_GEMM ((64 + 128) * LDK * 2 + 2048)
__global__ void __launch_bounds__(256, 3)
k_gemm(const float* __restrict__ x,
       const float* __restrict__ attn_l, const float* __restrict__ attn_r) {
    extern __shared__ __half sm[];
    __half* xs = sm;                       // [64][LDK]
    __half* Wt = sm + 64 * LDK;            // [128][LDK]
    float* sEl = (float*)(sm + 192 * LDK); // [64][4]
    float* sEr = sEl + 256;                // [64][4]

    const int t = threadIdx.x;
    const int lane = t & 31, warp = t >> 5;
    const int wm = warp >> 2, wn = warp & 3;   // warp grid 2m x 4n
    const int gid = lane >> 2, tig = lane & 3;
    const int row0 = blockIdx.x * 64;

    sEl[t] = 0.f;
    sEr[t] = 0.f;

#pragma unroll
    for (int i = 0; i < 8; i++) {
        int idx = i * 256 + t;
        int c = idx >> 4, kg = idx & 15;
        uint4 v = *(const uint4*)(g_Wh + c * 128 + kg * 8);
        *(uint4*)(Wt + c * LDK + kg * 8) = v;
    }
#pragma unroll
    for (int i = 0; i < 8; i++) {
        int idx = i * 256 + t;
        int r = idx >> 5, kg = idx & 31;
        float4 v = *(const float4*)(x + (size_t)(row0 + r) * 128 + kg * 4);
        __half2 h0 = __floats2half2_rn(v.x, v.y);
        __half2 h1 = __floats2half2_rn(v.z, v.w);
        uint2 pk;
        pk.x = *(unsigned*)&h0;
        pk.y = *(unsigned*)&h1;
        *(uint2*)(xs + r * LDK + kg * 4) = pk;
    }
    __syncthreads();

    float acc[2][4][4];
#pragma unroll
    for (int i = 0; i < 2; i++)
#pragma unroll
        for (int j = 0; j < 4; j++)
#pragma unroll
            for (int r = 0; r < 4; r++) acc[i][j][r] = 0.f;

#pragma unroll
    for (int ks = 0; ks < 8; ks++) {
        const int k0 = ks * 16;
        unsigned a[2][4];
#pragma unroll
        for (int mt = 0; mt < 2; mt++) {
            int rb = wm * 32 + mt * 16;
            a[mt][0] = *(const unsigned*)(xs + (rb + gid) * LDK + k0 + 2 * tig);
            a[mt][1] = *(const unsigned*)(xs + (rb + gid + 8) * LDK + k0 + 2 * tig);
            a[mt][2] = *(const unsigned*)(xs + (rb + gid) * LDK + k0 + 2 * tig + 8);
            a[mt][3] = *(const unsigned*)(xs + (rb + gid + 8) * LDK + k0 + 2 * tig + 8);
        }
#pragma unroll
        for (int nt = 0; nt < 4; nt++) {
            int cb = wn * 32 + nt * 8;
            unsigned b0 = *(const unsigned*)(Wt + (cb + gid) * LDK + k0 + 2 * tig);
            unsigned b1 = *(const unsigned*)(Wt + (cb + gid) * LDK + k0 + 2 * tig + 8);
#pragma unroll
            for (int mt = 0; mt < 2; mt++)
                mma_f16(acc[mt][nt], a[mt], b0, b1);
        }
    }

    // epilogue: store feat (fp16) + accumulate el/er into smem
#pragma unroll
    for (int mt = 0; mt < 2; mt++) {
        int lr0 = wm * 32 + mt * 16 + gid;
        int lr1 = lr0 + 8;
        float el0 = 0.f, el1 = 0.f, er0 = 0.f, er1 = 0.f;
#pragma unroll
        for (int nt = 0; nt < 4; nt++) {
            int c = wn * 32 + nt * 8 + tig * 2;
            float alc0 = attn_l[c], alc1 = attn_l[c + 1];
            float arc0 = attn_r[c], arc1 = attn_r[c + 1];
            float* a4 = acc[mt][nt];
            el0 += a4[0] * alc0 + a4[1] * alc1;
            er0 += a4[0] * arc0 + a4[1] * arc1;
            el1 += a4[2] * alc0 + a4[3] * alc1;
            er1 += a4[2] * arc0 + a4[3] * arc1;
            *(__half2*)(g_featH + (size_t)(row0 + lr0) * 128 + c) =
                __floats2half2_rn(a4[0], a4[1]);
            *(__half2*)(g_featH + (size_t)(row0 + lr1) * 128 + c) =
                __floats2half2_rn(a4[2], a4[3]);
        }
        atomicAdd(&sEl[lr0 * 4 + wn], el0);
        atomicAdd(&sEl[lr1 * 4 + wn], el1);
        atomicAdd(&sEr[lr0 * 4 + wn], er0);
        atomicAdd(&sEr[lr1 * 4 + wn], er1);
    }
    __syncthreads();
    // t in [0,256): 64 rows x 4 heads -> one (node, head) exp pair per thread
    {
        int r = t >> 2, hh = t & 3;
        size_t n = row0 + r;
        float el = sEl[r * 4 + hh];
        float er = sEr[r * 4 + hh];
        g_elp2[n * 4 + hh] = make_float2(__expf(el), __expf(GAT_SLOPE * el));
        g_erp2[n * 4 + hh] = make_float2(__expf(er), __expf(GAT_SLOPE * er));
    }
}

// ---------------- 2: fused edge-softmax + gather agg + BN partial stats -----
// grid (Nc), 128 threads: block = one node, warp = one batch, SYNC-FREE loop.
// lane = 4 channels (one uint2 = 8B gather per edge); per-edge weight is
// MUFU-free: t = p1*q1; w = (t>=1) ? t : p2*q2  (p/q = exp-factored terms,
// 8B broadcast loads). No smem staging; one sync only for the BN pre-reduce.
__global__ void __launch_bounds__(128, 16) k_agg() {
    const int n = blockIdx.x;
    const int tid = threadIdx.x;
    const int lane = tid & 31;         // channels 4*lane .. 4*lane+3
    const int b = tid >> 5;            // batch = warp
    const int h = lane >> 3;           // head
    const int off0 = g_off[n];
    const int deg  = g_off[n + 1] - off0;
    const size_t nb = (size_t)b * Nc + n;

    __shared__ float sS[4][HDc];      // [batch][channel] partial sums
    __shared__ float sQ[4][HDc];

    if (deg == 0) {
        *(uint2*)(g_aggH + nb * 128 + lane * 4) = make_uint2(0u, 0u);
        return;
    }

    const float2 q = g_erp2[nb * 4 + h];   // broadcast within 8-lane group

    float a0 = 0.f, a1 = 0.f, a2 = 0.f, a3 = 0.f, wsum = 0.f;

#pragma unroll 4
    for (int j = 0; j < deg; j++) {
        int s = __ldg(&g_csrc[off0 + j]);          // warp-broadcast load
        float2 p = g_elp2[((size_t)b * Nc + s) * 4 + h];
        uint2 u = *(const uint2*)(g_featH + ((size_t)b * Nc + s) * 128 + lane * 4);
        float tt = p.x * q.x;
        float w = (tt >= 1.f) ? tt : p.y * q.y;
        wsum += w;
        float2 f0 = __half22float2(*(const __half2*)&u.x);
        float2 f1 = __half22float2(*(const __half2*)&u.y);
        a0 += w * f0.x; a1 += w * f0.y;
        a2 += w * f1.x; a3 += w * f1.y;
    }

    float inv = 1.f / fmaxf(wsum, 1e-9f);
    float o0 = a0 * inv, o1 = a1 * inv, o2 = a2 * inv, o3 = a3 * inv;
    {
        __half2 h0 = __floats2half2_rn(o0, o1);
        __half2 h1 = __floats2half2_rn(o2, o3);
        uint2 pk;
        pk.x = *(unsigned*)&h0;
        pk.y = *(unsigned*)&h1;
        *(uint2*)(g_aggH + nb * 128 + lane * 4) = pk;
    }

    // BN partial stats from fp32 values: smem pre-reduce, then sliced atomics
    sS[b][lane * 4 + 0] = o0; sS[b][lane * 4 + 1] = o1;
    sS[b][lane * 4 + 2] = o2; sS[b][lane * 4 + 3] = o3;
    sQ[b][lane * 4 + 0] = o0 * o0; sQ[b][lane * 4 + 1] = o1 * o1;
    sQ[b][lane * 4 + 2] = o2 * o2; sQ[b][lane * 4 + 3] = o3 * o3;
    __syncthreads();
    {
        int ch = tid;  // 128 threads, 128 channels
        int sl = n & (NSLICE - 1);
        atomicAdd(&g_psum[sl][ch], sS[0][ch] + sS[1][ch] + sS[2][ch] + sS[3][ch]);
        atomicAdd(&g_psq[sl][ch],  sQ[0][ch] + sQ[1][ch] + sQ[2][ch] + sQ[3][ch]);
    }
}

// ---------------- 3: BN finalize + apply + LeakyReLU -------------------------
__global__ void __launch_bounds__(256)
k_bnapply(float4* out, const float* __restrict__ gamma,
          const float* __restrict__ beta) {
    __shared__ float s_sc[HDc];
    __shared__ float s_sh[HDc];
    const int tid = threadIdx.x;
    if (tid < HDc) {
        float s = 0.f, q = 0.f;
#pragma unroll
        for (int i = 0; i < NSLICE; i++) { s += g_psum[i][tid]; q += g_psq[i][tid]; }
        float mean = s / (float)BNc;
        float var  = q / (float)BNc - mean * mean;
        float sc = gamma[tid] * rsqrtf(var + BN_EPS);
        s_sc[tid] = sc;
        s_sh[tid] = beta[tid] - mean * sc;
    }
    __syncthreads();
    const int c4 = tid & 31;
    const float4 sc = *(const float4*)(s_sc + c4 * 4);
    const float4 sh = *(const float4*)(s_sh + c4 * 4);
    int r = blockIdx.x * 8 + (tid >> 5);
    const int rstride = gridDim.x * 8;
    for (; r < BNc; r += rstride) {
        uint2 u = *(const uint2*)(g_aggH + (size_t)r * 128 + c4 * 4);
        float2 f0 = __half22float2(*(const __half2*)&u.x);
        float2 f1 = __half22float2(*(const __half2*)&u.y);
        float4 v;
        v.x = leaky(f0.x * sc.x + sh.x, ACT_SLOPE);
        v.y = leaky(f0.y * sc.y + sh.y, ACT_SLOPE);
        v.z = leaky(f1.x * sc.z + sh.z, ACT_SLOPE);
        v.w = leaky(f1.y * sc.w + sh.w, ACT_SLOPE);
        out[(size_t)r * 32 + c4] = v;
    }
}

// ---------------- launch -----------------------------------------------------
extern "C" void kernel_launch(void* const* d_in, const int* in_sizes, int n_in,
                              void* d_out, int out_size) {
    const float* xx     = (const float*)d_in[0];
    const float* W      = (const float*)d_in[1];
    const float* attn_l = (const float*)d_in[2];
    const float* attn_r = (const float*)d_in[3];
    const float* gamma  = (const float*)d_in[4];
    const float* beta   = (const float*)d_in[5];
    const int*   src    = (const int*)d_in[6];
    const int*   dst    = (const int*)d_in[7];
    float* out = (float*)d_out;
    const int E = in_sizes[6];

    static cudaStream_t s2 = nullptr;
    static cudaEvent_t evFork = nullptr, evJoin = nullptr;
    if (s2 == nullptr) {
        cudaStreamCreateWithFlags(&s2, cudaStreamNonBlocking);
        cudaEventCreateWithFlags(&evFork, cudaEventDisableTiming);
        cudaEventCreateWithFlags(&evJoin, cudaEventDisableTiming);
        cudaFuncSetAttribute(k_gemm, cudaFuncAttributeMaxDynamicSharedMemorySize,
                             SMEM_GEMM);
    }

    // fork: CSR build on s2, W-prep + GEMM on main stream (independent work)
    cudaEventRecord(evFork, 0);
    cudaStreamWaitEvent(s2, evFork, 0);

    k_init<<<64, 256, 0, s2>>>();
    k_hist<<<(E + 511) / 512, 512, 0, s2>>>(dst, E);
    k_scan<<<1, 1024, 0, s2>>>();
    k_scatter<<<(E + 511) / 512, 512, 0, s2>>>(src, dst, E);
    cudaEventRecord(evJoin, s2);

    k_prepW<<<64, 256>>>(W);
    k_gemm<<<BNc / 64, 256, SMEM_GEMM>>>(xx, attn_l, attn_r);

    cudaStreamWaitEvent(0, evJoin, 0);

    k_agg<<<Nc, 128>>>();

    k_bnapply<<<2048, 256>>>((float4*)out, gamma, beta);
}